// round 6
// baseline (speedup 1.0000x reference)
#include <cuda_runtime.h>
#include <math.h>

#define T 2048
#define ESLOTS 64
#define VOCAB 50257
#define OUTW 50348   // 2 + 64 + 25 + 50257
#define NCTA 32

// ---------------- static device scratch ----------------
static __device__ __align__(16) float g_X[T * 256];
static __device__ __align__(16) float g_Xp[T * 1024];
static __device__ __align__(16) float g_H[T * 256];
static __device__ __align__(16) float g_WentH[T * 256];
static __device__ __align__(16) float g_WdH[T * 256];
static __device__ __align__(16) float g_E[T * 256];   // e_cur (pre-update) per step
static __device__ __align__(16) float g_U[T * 256];   // updated entity value per step
static __device__ __align__(16) float g_V[T * 256];   // h + We@e + We_b
static __device__ __align__(16) float g_ents[ESLOTS * 256];
static __device__ int   g_last[T * ESLOTS];
static __device__ __align__(16) float g_b2[1024];
static __device__ __align__(16) float g_q[2 * 256];
static __device__ __align__(16) float g_wrow[256];
static __device__ float g_gates[2][1024];
static __device__ unsigned g_cnt;

// ---------------- helpers ----------------
__device__ __forceinline__ unsigned ld_acq(const unsigned* p) {
    unsigned v;
    asm volatile("ld.acquire.gpu.global.u32 %0, [%1];" : "=r"(v) : "l"(p) : "memory");
    return v;
}
__device__ __forceinline__ float ld_vol(const float* p) {
    float v;
    asm volatile("ld.volatile.global.f32 %0, [%1];" : "=f"(v) : "l"(p) : "memory");
    return v;
}
__device__ __forceinline__ void st_vol(float* p, float v) {
    asm volatile("st.volatile.global.f32 [%0], %1;" :: "l"(p), "f"(v) : "memory");
}
__device__ __forceinline__ float wred(float s) {
    s += __shfl_xor_sync(0xffffffffu, s, 16);
    s += __shfl_xor_sync(0xffffffffu, s, 8);
    s += __shfl_xor_sync(0xffffffffu, s, 4);
    s += __shfl_xor_sync(0xffffffffu, s, 2);
    s += __shfl_xor_sync(0xffffffffu, s, 1);
    return s;
}
__device__ __forceinline__ float sigmoidf_(float x) { return 1.f / (1.f + expf(-x)); }

// ---------------- K0: gather embeddings, reset barrier counter ----------------
__global__ void k_gather(const int* __restrict__ tokens, const float* __restrict__ emb) {
    int t = blockIdx.x, tid = threadIdx.x;
    if (t == 0 && tid == 0) g_cnt = 0u;
    long long tok = tokens[t];
    g_X[(long long)t * 256 + tid] = emb[tok * 256 + tid];
}

// ---------------- K1: small precompute ----------------
__global__ void k_small(const float* __restrict__ b_ih, const float* __restrict__ b_hh,
                        const float* __restrict__ r_emb, const float* __restrict__ WrW,
                        const float* __restrict__ WentW) {
    int tid = threadIdx.x;  // 256
    for (int r = tid; r < 1024; r += 256) g_b2[r] = b_ih[r] + b_hh[r];
    for (int j = 0; j < 2; j++) {
        float s = 0.f;
        for (int k = 0; k < 256; k++) s = fmaf(r_emb[j * 256 + k], WrW[k * 256 + tid], s);
        g_q[j * 256 + tid] = s;
    }
    float s = 0.f;
    for (int j = 0; j < 256; j++) s += WentW[tid * 256 + j];
    g_wrow[tid] = s;
}

// ---------------- K2: last update step of slot i before t ----------------
__global__ void k_last(const int* __restrict__ eids) {
    int i = threadIdx.x;  // 64
    int last = -1;
    for (int t = 0; t < T; t++) {
        g_last[t * ESLOTS + i] = last;
        if (eids[t] == i) last = t;
    }
}

// ---------------- generic SGEMM: C[m,n]=sum_k A[m,k]*B[n,k] (+bias[n]) (+Add[m,n]) ----------------
__global__ void __launch_bounds__(256) sgemm256(
        const float* __restrict__ A, const float* __restrict__ B,
        const float* __restrict__ bias, const float* __restrict__ Add,
        float* __restrict__ C, int N, long long cstride, long long coff) {
    __shared__ float As[8][128];
    __shared__ float Bs[8][128];
    int tid = threadIdx.x;
    int m0 = blockIdx.y * 128;
    int n0 = blockIdx.x * 128;
    int tx = tid & 15, ty = tid >> 4;
    int lrow = tid >> 1;
    int lcg = (tid & 1) * 4;

    float acc[8][8];
#pragma unroll
    for (int i = 0; i < 8; i++)
#pragma unroll
        for (int j = 0; j < 8; j++) acc[i][j] = 0.f;

    for (int k0 = 0; k0 < 256; k0 += 8) {
        float4 a4 = *(const float4*)(A + (long long)(m0 + lrow) * 256 + k0 + lcg);
        int brow = n0 + lrow;
        float4 b4 = make_float4(0.f, 0.f, 0.f, 0.f);
        if (brow < N) b4 = *(const float4*)(B + (long long)brow * 256 + k0 + lcg);
        __syncthreads();
        As[lcg + 0][lrow] = a4.x; As[lcg + 1][lrow] = a4.y;
        As[lcg + 2][lrow] = a4.z; As[lcg + 3][lrow] = a4.w;
        Bs[lcg + 0][lrow] = b4.x; Bs[lcg + 1][lrow] = b4.y;
        Bs[lcg + 2][lrow] = b4.z; Bs[lcg + 3][lrow] = b4.w;
        __syncthreads();
#pragma unroll
        for (int kk = 0; kk < 8; kk++) {
            float a[8], b[8];
            *(float4*)(a)     = *(const float4*)(&As[kk][ty * 8]);
            *(float4*)(a + 4) = *(const float4*)(&As[kk][ty * 8 + 4]);
#pragma unroll
            for (int j = 0; j < 8; j++) b[j] = Bs[kk][tx + 16 * j];
#pragma unroll
            for (int i = 0; i < 8; i++)
#pragma unroll
                for (int j = 0; j < 8; j++) acc[i][j] = fmaf(a[i], b[j], acc[i][j]);
        }
    }
#pragma unroll
    for (int i = 0; i < 8; i++) {
        long long m = m0 + ty * 8 + i;
        const float* addrow = Add ? (Add + m * 256) : (const float*)0;
        float* crow = C + m * cstride + coff;
#pragma unroll
        for (int j = 0; j < 8; j++) {
            int n = n0 + tx + 16 * j;
            if (n < N) {
                float v = acc[i][j];
                if (bias) v += bias[n];
                if (addrow) v += addrow[n];
                crow[n] = v;
            }
        }
    }
}

// ---------------- K3: cooperative sequential LSTM (32 CTAs x 256 thr) ----------------
__global__ void __launch_bounds__(256) k_lstm(const float* __restrict__ Xp,
                                              const float* __restrict__ Whh,
                                              float* __restrict__ Hout) {
    __shared__ float sw[32][256];
    __shared__ float sh[256];
    int tid = threadIdx.x;
    int cta = blockIdx.x;
    int r0 = cta * 32;
    int warp = tid >> 5, lane = tid & 31;

    const float4* src = (const float4*)(Whh + (long long)r0 * 256);
    float4* dst = (float4*)(&sw[0][0]);
    for (int i = tid; i < 32 * 256 / 4; i += 256) dst[i] = src[i];
    sh[tid] = 0.f;
    float c = 0.f;
    __syncthreads();

    for (int t = 0; t < T; t++) {
        float hreg[8];
#pragma unroll
        for (int i = 0; i < 8; i++) hreg[i] = sh[lane + 32 * i];
        float* gbuf = g_gates[t & 1];
#pragma unroll
        for (int rr = 0; rr < 4; rr++) {
            int rl = warp * 4 + rr;
            float s = 0.f;
#pragma unroll
            for (int i = 0; i < 8; i++) s = fmaf(sw[rl][lane + 32 * i], hreg[i], s);
            s = wred(s);
            if (lane == 0)
                st_vol(&gbuf[r0 + rl], s + __ldg(&Xp[(long long)t * 1024 + r0 + rl]));
        }
        __threadfence();
        __syncthreads();
        if (tid == 0) {
            atomicAdd(&g_cnt, 1u);
            unsigned target = (unsigned)NCTA * (unsigned)(t + 1);
            while (ld_acq(&g_cnt) < target) {}
        }
        __syncthreads();
        float gi = ld_vol(&gbuf[tid]);
        float gf = ld_vol(&gbuf[256 + tid]);
        float gg = ld_vol(&gbuf[512 + tid]);
        float go = ld_vol(&gbuf[768 + tid]);
        c = sigmoidf_(gf) * c + sigmoidf_(gi) * tanhf(gg);
        float h = sigmoidf_(go) * tanhf(c);
        sh[tid] = h;
        if (cta == 0) Hout[(long long)t * 256 + tid] = h;
        __syncthreads();
    }
}

// ---------------- K4: sequential entity-value chain (1 warp) ----------------
__global__ void k_entity(const int* __restrict__ eids, const float* __restrict__ H,
                         const float* __restrict__ WdH, const float* __restrict__ ents_init,
                         const float* __restrict__ Wdelta_b,
                         float* __restrict__ Eout, float* __restrict__ Uout) {
    int lane = threadIdx.x;  // 32
    for (int i = lane; i < ESLOTS * 256; i += 32) g_ents[i] = ents_init[i];
    float wdb = Wdelta_b[0];
    for (int t = 0; t < T; t++) {
        int eid = eids[t];
        long long base = (long long)eid * 256 + lane;
        long long tb = (long long)t * 256 + lane;
        float e[8], wd[8], h[8];
#pragma unroll
        for (int i = 0; i < 8; i++) e[i] = g_ents[base + 32 * i];
#pragma unroll
        for (int i = 0; i < 8; i++) wd[i] = __ldg(&WdH[tb + 32 * i]);
#pragma unroll
        for (int i = 0; i < 8; i++) h[i] = __ldg(&H[tb + 32 * i]);
        float d = 0.f;
#pragma unroll
        for (int i = 0; i < 8; i++) d = fmaf(e[i], wd[i], d);
        d = wred(d);
        float delta = sigmoidf_(d + wdb);
        float u[8];
        float ss = 0.f;
#pragma unroll
        for (int i = 0; i < 8; i++) {
            u[i] = delta * e[i] + (1.f - delta) * h[i];
            ss = fmaf(u[i], u[i], ss);
        }
        ss = wred(ss);
        float rn = 1.f / sqrtf(ss);
#pragma unroll
        for (int i = 0; i < 8; i++) {
            float uv = u[i] * rn;
            g_ents[base + 32 * i] = uv;
            Uout[tb + 32 * i] = uv;
            Eout[tb + 32 * i] = e[i];
        }
    }
}

// ---------------- K5: heads -> pred_r (2), pred_e (64), pred_l (25) ----------------
__global__ void __launch_bounds__(256) k_heads(
        const float* __restrict__ ents_init, const float* __restrict__ dist_init,
        const float* __restrict__ WlenW, const float* __restrict__ Wlenb,
        const float* __restrict__ Wrb, const float* __restrict__ Wentb,
        const float* __restrict__ wdW, const float* __restrict__ wdb_,
        float* __restrict__ out) {
    __shared__ float sh[256], se[256], swt[256];
    int t = blockIdx.x;
    int tid = threadIdx.x;
    int warp = tid >> 5, lane = tid & 31;
    long long tb = (long long)t * 256;
    sh[tid] = g_H[tb + tid];
    se[tid] = g_E[tb + tid];
    swt[tid] = g_WentH[tb + tid];
    float wr[8];
#pragma unroll
    for (int i = 0; i < 8; i++) wr[i] = g_wrow[lane + 32 * i];
    __syncthreads();

    float wdw = wdW[0], wdb = wdb_[0], wentb = Wentb[0];
    float* orow = out + (long long)t * OUTW;

    // pred_e: warp handles slots {warp, warp+8, ...}
#pragma unroll
    for (int ssi = 0; ssi < 8; ssi++) {
        int s = warp + ssi * 8;
        int li = g_last[t * ESLOTS + s];
        const float* sv = (li < 0) ? (ents_init + (long long)s * 256)
                                   : (g_U + (long long)li * 256);
        float d1 = 0.f, d2 = 0.f;
#pragma unroll
        for (int i = 0; i < 8; i++) {
            float v = sv[lane + 32 * i];
            d1 = fmaf(v, swt[lane + 32 * i], d1);
            d2 = fmaf(v, wr[i], d2);
        }
        d1 = wred(d1);
        d2 = wred(d2);
        if (lane == 0) {
            float dist = ((li < 0) ? dist_init[s] : (float)li) - (float)t;
            orow[2 + s] = d1 + (dist * wdw + wdb) * d2 + wentb;
        }
    }

    // pred_r: warps 0,1
    if (warp < 2) {
        float d = 0.f;
#pragma unroll
        for (int i = 0; i < 8; i++)
            d = fmaf(g_q[warp * 256 + lane + 32 * i], sh[lane + 32 * i], d);
        d = wred(d);
        if (lane == 0) orow[warp] = d + Wrb[0];
    }

    // pred_l: 25 rows, warp handles {warp, warp+8, warp+16, warp+24}
#pragma unroll
    for (int rr = 0; rr < 4; rr++) {
        int l = warp + rr * 8;
        if (l < 25) {
            float d = 0.f;
#pragma unroll
            for (int i = 0; i < 16; i++) {
                int idx = lane + 32 * i;
                float x = (idx < 256) ? sh[idx] : se[idx - 256];
                d = fmaf(WlenW[(long long)l * 512 + idx], x, d);
            }
            d = wred(d);
            if (lane == 0) orow[66 + l] = d + Wlenb[l];
        }
    }
}

// ---------------- launch ----------------
extern "C" void kernel_launch(void* const* d_in, const int* in_sizes, int n_in,
                              void* d_out, int out_size) {
    const int*   tokens  = (const int*)d_in[0];
    const int*   eids    = (const int*)d_in[1];
    const float* emb     = (const float*)d_in[2];
    const float* W_ih    = (const float*)d_in[3];
    const float* W_hh    = (const float*)d_in[4];
    const float* b_ih    = (const float*)d_in[5];
    const float* b_hh    = (const float*)d_in[6];
    const float* out_W   = (const float*)d_in[7];
    const float* out_b   = (const float*)d_in[8];
    const float* r_emb   = (const float*)d_in[9];
    const float* Wr_W    = (const float*)d_in[10];
    const float* Wr_b    = (const float*)d_in[11];
    const float* Wlen_W  = (const float*)d_in[12];
    const float* Wlen_b  = (const float*)d_in[13];
    const float* Went_W  = (const float*)d_in[14];
    const float* Went_b  = (const float*)d_in[15];
    const float* wdist_W = (const float*)d_in[16];
    const float* wdist_b = (const float*)d_in[17];
    const float* Wd_W    = (const float*)d_in[18];
    const float* Wd_b    = (const float*)d_in[19];
    const float* We_W    = (const float*)d_in[20];
    const float* We_b    = (const float*)d_in[21];
    const float* ents0   = (const float*)d_in[22];
    const float* dist0   = (const float*)d_in[23];
    float* out = (float*)d_out;

    float *gX, *gXp, *gH, *gWentH, *gWdH, *gE, *gU, *gV, *gb2;
    cudaGetSymbolAddress((void**)&gX, g_X);
    cudaGetSymbolAddress((void**)&gXp, g_Xp);
    cudaGetSymbolAddress((void**)&gH, g_H);
    cudaGetSymbolAddress((void**)&gWentH, g_WentH);
    cudaGetSymbolAddress((void**)&gWdH, g_WdH);
    cudaGetSymbolAddress((void**)&gE, g_E);
    cudaGetSymbolAddress((void**)&gU, g_U);
    cudaGetSymbolAddress((void**)&gV, g_V);
    cudaGetSymbolAddress((void**)&gb2, g_b2);

    k_gather<<<T, 256>>>(tokens, emb);
    k_small<<<1, 256>>>(b_ih, b_hh, r_emb, Wr_W, Went_W);
    k_last<<<1, ESLOTS>>>(eids);

    // Xp = X @ W_ih^T + (b_ih + b_hh)
    sgemm256<<<dim3(8, 16), 256>>>(gX, W_ih, gb2, (const float*)0, gXp,
                                   1024, 1024, 0);
    // sequential LSTM -> H
    k_lstm<<<NCTA, 256>>>(gXp, W_hh, gH);
    // WentH = H @ Went^T ; WdH = H @ Wdelta^T
    sgemm256<<<dim3(2, 16), 256>>>(gH, Went_W, (const float*)0, (const float*)0,
                                   gWentH, 256, 256, 0);
    sgemm256<<<dim3(2, 16), 256>>>(gH, Wd_W, (const float*)0, (const float*)0,
                                   gWdH, 256, 256, 0);
    // sequential entity chain -> E (pre), U (post)
    k_entity<<<1, 32>>>(eids, gH, gWdH, ents0, Wd_b, gE, gU);
    // V = H + E @ We^T + We_b
    sgemm256<<<dim3(2, 16), 256>>>(gE, We_W, We_b, gH, gV, 256, 256, 0);
    // heads: pred_r / pred_e / pred_l -> out cols [0,91)
    k_heads<<<T, 256>>>(ents0, dist0, Wlen_W, Wlen_b, Wr_b, Went_b,
                        wdist_W, wdist_b, out);
    // pred_x = V @ out_W^T + out_b -> out cols [91, 50348)
    sgemm256<<<dim3((VOCAB + 127) / 128, 16), 256>>>(gV, out_W, out_b,
                                                     (const float*)0, out,
                                                     VOCAB, OUTW, 91);
}

// round 8
// speedup vs baseline: 1.2222x; 1.2222x over previous
#include <cuda_runtime.h>
#include <math.h>

#define T 2048
#define ESLOTS 64
#define VOCAB 50257
#define OUTW 50348   // 2 + 64 + 25 + 50257
#define NCTA 32

// ---------------- static device scratch ----------------
static __device__ __align__(16) float g_X[T * 256];
static __device__ __align__(16) float g_Xp[T * 1024];
static __device__ __align__(16) float g_H[T * 256];
static __device__ __align__(16) float g_WentH[T * 256];
static __device__ __align__(16) float g_WdH[T * 256];
static __device__ __align__(16) float g_E[T * 256];   // e_cur (pre-update) per step
static __device__ __align__(16) float g_U[T * 256];   // updated entity value per step
static __device__ __align__(16) float g_V[T * 256];   // h + We@e + We_b
static __device__ int   g_last[T * ESLOTS];
static __device__ __align__(16) float g_b2[1024];
static __device__ __align__(16) float g_q[2 * 256];
static __device__ __align__(16) float g_wrow[256];
static __device__ float g_gates[2][1024];
static __device__ unsigned g_cnt;

// ---------------- helpers ----------------
__device__ __forceinline__ unsigned ld_acq(const unsigned* p) {
    unsigned v;
    asm volatile("ld.acquire.gpu.global.u32 %0, [%1];" : "=r"(v) : "l"(p) : "memory");
    return v;
}
__device__ __forceinline__ void red_release(unsigned* p) {
    asm volatile("red.release.gpu.global.add.u32 [%0], 1;" :: "l"(p) : "memory");
}
__device__ __forceinline__ float ld_vol(const float* p) {
    float v;
    asm volatile("ld.volatile.global.f32 %0, [%1];" : "=f"(v) : "l"(p) : "memory");
    return v;
}
__device__ __forceinline__ void st_vol(float* p, float v) {
    asm volatile("st.volatile.global.f32 [%0], %1;" :: "l"(p), "f"(v) : "memory");
}
__device__ __forceinline__ float wred(float s) {
    s += __shfl_xor_sync(0xffffffffu, s, 16);
    s += __shfl_xor_sync(0xffffffffu, s, 8);
    s += __shfl_xor_sync(0xffffffffu, s, 4);
    s += __shfl_xor_sync(0xffffffffu, s, 2);
    s += __shfl_xor_sync(0xffffffffu, s, 1);
    return s;
}
__device__ __forceinline__ float sigmoidf_(float x) { return 1.f / (1.f + expf(-x)); }

// ---------------- K0: gather embeddings, reset barrier counter ----------------
__global__ void k_gather(const int* __restrict__ tokens, const float* __restrict__ emb) {
    int t = blockIdx.x, tid = threadIdx.x;
    if (t == 0 && tid == 0) g_cnt = 0u;
    long long tok = tokens[t];
    g_X[(long long)t * 256 + tid] = emb[tok * 256 + tid];
}

// ---------------- K1: small precompute ----------------
__global__ void k_small(const float* __restrict__ b_ih, const float* __restrict__ b_hh,
                        const float* __restrict__ r_emb, const float* __restrict__ WrW,
                        const float* __restrict__ WentW) {
    int tid = threadIdx.x;  // 256
    for (int r = tid; r < 1024; r += 256) g_b2[r] = b_ih[r] + b_hh[r];
    for (int j = 0; j < 2; j++) {
        float s = 0.f;
        for (int k = 0; k < 256; k++) s = fmaf(r_emb[j * 256 + k], WrW[k * 256 + tid], s);
        g_q[j * 256 + tid] = s;
    }
    float s = 0.f;
    for (int j = 0; j < 256; j++) s += WentW[tid * 256 + j];
    g_wrow[tid] = s;
}

// ---------------- K2: last update step of slot i before t (64 threads, smem eids) ----------------
__global__ void k_last(const int* __restrict__ eids) {
    __shared__ int se[T];
    int i = threadIdx.x;  // 64
    for (int j = i; j < T; j += 64) se[j] = eids[j];
    __syncthreads();
    int last = -1;
#pragma unroll 8
    for (int t = 0; t < T; t++) {
        g_last[t * ESLOTS + i] = last;
        if (se[t] == i) last = t;
    }
}

// ---------------- SGEMM: C[m,n]=sum_k A[m,k]*B[n,k] (+bias[n]) (+Add[m,n]) ----------------
// A: [M,256], B: [N,256] row-major. 128x128 tile, ktile=8, double-buffered.
// grid = (m_tiles, n_tiles)
__global__ void __launch_bounds__(256) sgemm256(
        const float* __restrict__ A, const float* __restrict__ B,
        const float* __restrict__ bias, const float* __restrict__ Add,
        float* __restrict__ C, int N, long long cstride, long long coff) {
    __shared__ float As[2][8][132];
    __shared__ float Bs[2][8][132];
    int tid = threadIdx.x;
    int m0 = blockIdx.x * 128;
    int n0 = blockIdx.y * 128;
    int tx = tid & 15, ty = tid >> 4;
    int lrow = tid >> 1;
    int lcg = (tid & 1) * 4;

    const float* Aptr = A + (long long)(m0 + lrow) * 256 + lcg;
    int brow = n0 + lrow;
    bool bvalid = brow < N;
    const float* Bptr = B + (long long)brow * 256 + lcg;

    float acc[8][8];
#pragma unroll
    for (int i = 0; i < 8; i++)
#pragma unroll
        for (int j = 0; j < 8; j++) acc[i][j] = 0.f;

    // stage 0
    {
        float4 a4 = *(const float4*)(Aptr);
        float4 b4 = bvalid ? *(const float4*)(Bptr) : make_float4(0.f, 0.f, 0.f, 0.f);
        As[0][lcg + 0][lrow] = a4.x; As[0][lcg + 1][lrow] = a4.y;
        As[0][lcg + 2][lrow] = a4.z; As[0][lcg + 3][lrow] = a4.w;
        Bs[0][lcg + 0][lrow] = b4.x; Bs[0][lcg + 1][lrow] = b4.y;
        Bs[0][lcg + 2][lrow] = b4.z; Bs[0][lcg + 3][lrow] = b4.w;
    }
    __syncthreads();

    int buf = 0;
    for (int k0 = 8; k0 <= 256; k0 += 8) {
        float4 na, nb;
        bool more = (k0 < 256);
        if (more) {
            na = *(const float4*)(Aptr + k0);
            nb = bvalid ? *(const float4*)(Bptr + k0) : make_float4(0.f, 0.f, 0.f, 0.f);
        }
#pragma unroll
        for (int kk = 0; kk < 8; kk++) {
            float a[8], b[8];
            *(float4*)(a)     = *(const float4*)(&As[buf][kk][ty * 8]);
            *(float4*)(a + 4) = *(const float4*)(&As[buf][kk][ty * 8 + 4]);
            *(float4*)(b)     = *(const float4*)(&Bs[buf][kk][tx * 4]);
            *(float4*)(b + 4) = *(const float4*)(&Bs[buf][kk][64 + tx * 4]);
#pragma unroll
            for (int i = 0; i < 8; i++)
#pragma unroll
                for (int j = 0; j < 8; j++) acc[i][j] = fmaf(a[i], b[j], acc[i][j]);
        }
        if (more) {
            int nbuf = buf ^ 1;
            As[nbuf][lcg + 0][lrow] = na.x; As[nbuf][lcg + 1][lrow] = na.y;
            As[nbuf][lcg + 2][lrow] = na.z; As[nbuf][lcg + 3][lrow] = na.w;
            Bs[nbuf][lcg + 0][lrow] = nb.x; Bs[nbuf][lcg + 1][lrow] = nb.y;
            Bs[nbuf][lcg + 2][lrow] = nb.z; Bs[nbuf][lcg + 3][lrow] = nb.w;
            __syncthreads();
            buf = nbuf;
        }
    }

#pragma unroll
    for (int i = 0; i < 8; i++) {
        long long m = m0 + ty * 8 + i;
        const float* addrow = Add ? (Add + m * 256) : (const float*)0;
        float* crow = C + m * cstride + coff;
#pragma unroll
        for (int j = 0; j < 8; j++) {
            int n = n0 + ((j < 4) ? (tx * 4 + j) : (64 + tx * 4 + (j - 4)));
            if (n < N) {
                float v = acc[i][j];
                if (bias) v += bias[n];
                if (addrow) v += addrow[n];
                crow[n] = v;
            }
        }
    }
}

// ---------------- K3: cooperative sequential LSTM (32 CTAs x 256 thr) ----------------
__global__ void __launch_bounds__(256) k_lstm(const float* __restrict__ Xp,
                                              const float* __restrict__ Whh,
                                              float* __restrict__ Hout) {
    __shared__ float sw[32][256];
    __shared__ float sh[256];
    int tid = threadIdx.x;
    int cta = blockIdx.x;
    int r0 = cta * 32;
    int warp = tid >> 5, lane = tid & 31;

    const float4* src = (const float4*)(Whh + (long long)r0 * 256);
    float4* dst = (float4*)(&sw[0][0]);
    for (int i = tid; i < 32 * 256 / 4; i += 256) dst[i] = src[i];
    sh[tid] = 0.f;
    float c = 0.f;
    __syncthreads();

    for (int t = 0; t < T; t++) {
        // prefetch input-gate contribution (off the h-dependent path)
        float xp[4];
#pragma unroll
        for (int rr = 0; rr < 4; rr++)
            xp[rr] = __ldg(&Xp[(long long)t * 1024 + r0 + warp * 4 + rr]);
        float hreg[8];
#pragma unroll
        for (int i = 0; i < 8; i++) hreg[i] = sh[lane + 32 * i];
        float* gbuf = g_gates[t & 1];
#pragma unroll
        for (int rr = 0; rr < 4; rr++) {
            int rl = warp * 4 + rr;
            float s = 0.f;
#pragma unroll
            for (int i = 0; i < 8; i++) s = fmaf(sw[rl][lane + 32 * i], hreg[i], s);
            s = wred(s);
            if (lane == 0) st_vol(&gbuf[r0 + rl], s + xp[rr]);
        }
        __syncthreads();
        if (tid == 0) {
            red_release(&g_cnt);   // cumulative release: covers all warps' gate stores
            unsigned target = (unsigned)NCTA * (unsigned)(t + 1);
            while (ld_acq(&g_cnt) < target) {}
        }
        __syncthreads();
        float gi = ld_vol(&gbuf[tid]);
        float gf = ld_vol(&gbuf[256 + tid]);
        float gg = ld_vol(&gbuf[512 + tid]);
        float go = ld_vol(&gbuf[768 + tid]);
        c = sigmoidf_(gf) * c + sigmoidf_(gi) * tanhf(gg);
        float h = sigmoidf_(go) * tanhf(c);
        sh[tid] = h;
        if (cta == 0) Hout[(long long)t * 256 + tid] = h;
        __syncthreads();
    }
}

// ---------------- K4: entity chains, one warp per slot (64 independent chains) ----------------
__global__ void __launch_bounds__(1024) k_entity2(
        const int* __restrict__ eids, const float* __restrict__ H,
        const float* __restrict__ WdH, const float* __restrict__ ents_init,
        const float* __restrict__ Wdelta_b,
        float* __restrict__ Eout, float* __restrict__ Uout) {
    int slot = blockIdx.x * 32 + (threadIdx.x >> 5);  // 2 CTAs x 32 warps = 64 slots
    int lane = threadIdx.x & 31;
    float e[8];
#pragma unroll
    for (int i = 0; i < 8; i++) e[i] = ents_init[(long long)slot * 256 + lane + 32 * i];
    float wdb = Wdelta_b[0];

    for (int t0 = 0; t0 < T; t0 += 32) {
        int myeid = eids[t0 + lane];
        unsigned mask = __ballot_sync(0xffffffffu, myeid == slot);
        while (mask) {
            int b = __ffs(mask) - 1;
            mask &= mask - 1;
            long long tb = (long long)(t0 + b) * 256 + lane;
            float wd[8], h[8];
#pragma unroll
            for (int i = 0; i < 8; i++) wd[i] = __ldg(&WdH[tb + 32 * i]);
#pragma unroll
            for (int i = 0; i < 8; i++) h[i] = __ldg(&H[tb + 32 * i]);
            float d = 0.f;
#pragma unroll
            for (int i = 0; i < 8; i++) d = fmaf(e[i], wd[i], d);
            d = wred(d);
            float delta = sigmoidf_(d + wdb);
            float u[8], ss = 0.f;
#pragma unroll
            for (int i = 0; i < 8; i++) {
                u[i] = delta * e[i] + (1.f - delta) * h[i];
                ss = fmaf(u[i], u[i], ss);
            }
            ss = wred(ss);
            float rn = 1.f / sqrtf(ss);
#pragma unroll
            for (int i = 0; i < 8; i++) {
                Eout[tb + 32 * i] = e[i];
                float uv = u[i] * rn;
                Uout[tb + 32 * i] = uv;
                e[i] = uv;
            }
        }
    }
}

// ---------------- K5: heads -> pred_r (2), pred_e (64), pred_l (25) ----------------
__global__ void __launch_bounds__(256) k_heads(
        const float* __restrict__ ents_init, const float* __restrict__ dist_init,
        const float* __restrict__ WlenW, const float* __restrict__ Wlenb,
        const float* __restrict__ Wrb, const float* __restrict__ Wentb,
        const float* __restrict__ wdW, const float* __restrict__ wdb_,
        float* __restrict__ out) {
    __shared__ float sh[256], se[256], swt[256];
    int t = blockIdx.x;
    int tid = threadIdx.x;
    int warp = tid >> 5, lane = tid & 31;
    long long tb = (long long)t * 256;
    sh[tid] = g_H[tb + tid];
    se[tid] = g_E[tb + tid];
    swt[tid] = g_WentH[tb + tid];
    float wr[8];
#pragma unroll
    for (int i = 0; i < 8; i++) wr[i] = g_wrow[lane + 32 * i];
    __syncthreads();

    float wdw = wdW[0], wdb = wdb_[0], wentb = Wentb[0];
    float* orow = out + (long long)t * OUTW;

#pragma unroll
    for (int ssi = 0; ssi < 8; ssi++) {
        int s = warp + ssi * 8;
        int li = g_last[t * ESLOTS + s];
        const float* sv = (li < 0) ? (ents_init + (long long)s * 256)
                                   : (g_U + (long long)li * 256);
        float d1 = 0.f, d2 = 0.f;
#pragma unroll
        for (int i = 0; i < 8; i++) {
            float v = sv[lane + 32 * i];
            d1 = fmaf(v, swt[lane + 32 * i], d1);
            d2 = fmaf(v, wr[i], d2);
        }
        d1 = wred(d1);
        d2 = wred(d2);
        if (lane == 0) {
            float dist = ((li < 0) ? dist_init[s] : (float)li) - (float)t;
            orow[2 + s] = d1 + (dist * wdw + wdb) * d2 + wentb;
        }
    }

    if (warp < 2) {
        float d = 0.f;
#pragma unroll
        for (int i = 0; i < 8; i++)
            d = fmaf(g_q[warp * 256 + lane + 32 * i], sh[lane + 32 * i], d);
        d = wred(d);
        if (lane == 0) orow[warp] = d + Wrb[0];
    }

#pragma unroll
    for (int rr = 0; rr < 4; rr++) {
        int l = warp + rr * 8;
        if (l < 25) {
            float d = 0.f;
#pragma unroll
            for (int i = 0; i < 16; i++) {
                int idx = lane + 32 * i;
                float x = (idx < 256) ? sh[idx] : se[idx - 256];
                d = fmaf(WlenW[(long long)l * 512 + idx], x, d);
            }
            d = wred(d);
            if (lane == 0) orow[66 + l] = d + Wlenb[l];
        }
    }
}

// ---------------- launch ----------------
extern "C" void kernel_launch(void* const* d_in, const int* in_sizes, int n_in,
                              void* d_out, int out_size) {
    const int*   tokens  = (const int*)d_in[0];
    const int*   eids    = (const int*)d_in[1];
    const float* emb     = (const float*)d_in[2];
    const float* W_ih    = (const float*)d_in[3];
    const float* W_hh    = (const float*)d_in[4];
    const float* b_ih    = (const float*)d_in[5];
    const float* b_hh    = (const float*)d_in[6];
    const float* out_W   = (const float*)d_in[7];
    const float* out_b   = (const float*)d_in[8];
    const float* r_emb   = (const float*)d_in[9];
    const float* Wr_W    = (const float*)d_in[10];
    const float* Wr_b    = (const float*)d_in[11];
    const float* Wlen_W  = (const float*)d_in[12];
    const float* Wlen_b  = (const float*)d_in[13];
    const float* Went_W  = (const float*)d_in[14];
    const float* Went_b  = (const float*)d_in[15];
    const float* wdist_W = (const float*)d_in[16];
    const float* wdist_b = (const float*)d_in[17];
    const float* Wd_W    = (const float*)d_in[18];
    const float* Wd_b    = (const float*)d_in[19];
    const float* We_W    = (const float*)d_in[20];
    const float* We_b    = (const float*)d_in[21];
    const float* ents0   = (const float*)d_in[22];
    const float* dist0   = (const float*)d_in[23];
    float* out = (float*)d_out;

    float *gX, *gXp, *gH, *gWentH, *gWdH, *gE, *gU, *gV, *gb2;
    cudaGetSymbolAddress((void**)&gX, g_X);
    cudaGetSymbolAddress((void**)&gXp, g_Xp);
    cudaGetSymbolAddress((void**)&gH, g_H);
    cudaGetSymbolAddress((void**)&gWentH, g_WentH);
    cudaGetSymbolAddress((void**)&gWdH, g_WdH);
    cudaGetSymbolAddress((void**)&gE, g_E);
    cudaGetSymbolAddress((void**)&gU, g_U);
    cudaGetSymbolAddress((void**)&gV, g_V);
    cudaGetSymbolAddress((void**)&gb2, g_b2);

    k_gather<<<T, 256>>>(tokens, emb);
    k_small<<<1, 256>>>(b_ih, b_hh, r_emb, Wr_W, Went_W);
    k_last<<<1, ESLOTS>>>(eids);

    // Xp = X @ W_ih^T + (b_ih + b_hh)     grid = (m_tiles=16, n_tiles=8)
    sgemm256<<<dim3(16, 8), 256>>>(gX, W_ih, gb2, (const float*)0, gXp,
                                   1024, 1024, 0);
    // sequential LSTM -> H
    k_lstm<<<NCTA, 256>>>(gXp, W_hh, gH);
    // WentH = H @ Went^T ; WdH = H @ Wdelta^T
    sgemm256<<<dim3(16, 2), 256>>>(gH, Went_W, (const float*)0, (const float*)0,
                                   gWentH, 256, 256, 0);
    sgemm256<<<dim3(16, 2), 256>>>(gH, Wd_W, (const float*)0, (const float*)0,
                                   gWdH, 256, 256, 0);
    // entity chains (64 warps, one per slot) -> E (pre), U (post)
    k_entity2<<<2, 1024>>>(eids, gH, gWdH, ents0, Wd_b, gE, gU);
    // V = H + E @ We^T + We_b
    sgemm256<<<dim3(16, 2), 256>>>(gE, We_W, We_b, gH, gV, 256, 256, 0);
    // heads: pred_r / pred_e / pred_l -> out cols [0,91)
    k_heads<<<T, 256>>>(ents0, dist0, Wlen_W, Wlen_b, Wr_b, Went_b,
                        wdist_W, wdist_b, out);
    // pred_x = V @ out_W^T + out_b -> out cols [91, 50348)
    sgemm256<<<dim3(16, (VOCAB + 127) / 128), 256>>>(gV, out_W, out_b,
                                                     (const float*)0, out,
                                                     VOCAB, OUTW, 91);
}